// round 4
// baseline (speedup 1.0000x reference)
#include <cuda_runtime.h>
#include <cstdint>

// ============================================================================
// PointAttention2: out[b,0,g] = sum_{o<256} Wv[o%32]*tanh(qc[b][o] + e[b,g,o]) + 8*bv
//   qc = query@Wq.T + bq + be (tiny),  e = ref@We.T  (34 GFLOP GEMM).
// ptxas target is base sm_103 (no 'a') -> tcgen05 unavailable. GEMM runs on
// the base-ISA tensor path: mma.sync.aligned.m16n8k8 tf32 (HMMA), cp.async
// 3-stage pipeline, fused register epilogue.
// ============================================================================

#define B_DIM   256
#define G_DIM   1024
#define H_DIM   256
#define TM      128                 // rows per CTA
#define KC      32                  // K chunk (floats)
#define NCH     8                   // 256/32
#define STAGES  3
#define STAGE_FLOATS (128*32 + 256*32)   // A(4096) + B(8192) = 12288 floats = 48KB
#define SM_STAGE_F   512            // stages start at float offset 512 (byte 2048)
#define SMEM_TOTAL   ((SM_STAGE_F + STAGES*STAGE_FLOATS) * 4)   // 149504 B

__device__ float g_qc[B_DIM * H_DIM];   // q[b][o] + bq[o] + be[o]

// ---------------- helpers ----------------
__device__ __forceinline__ uint32_t smem_u32(const void* p) {
    uint32_t a;
    asm("{ .reg .u64 t; cvta.to.shared.u64 t, %1; cvt.u32.u64 %0, t; }" : "=r"(a) : "l"(p));
    return a;
}
__device__ __forceinline__ void cp16(uint32_t dst, const float* src) {
    asm volatile("cp.async.cg.shared.global [%0], [%1], 16;" :: "r"(dst), "l"(src) : "memory");
}
__device__ __forceinline__ uint32_t f2tf(float x) {   // round-to-nearest tf32
    uint32_t r;
    asm("cvt.rna.tf32.f32 %0, %1;" : "=r"(r) : "f"(x));
    return r;
}
__device__ __forceinline__ void mma8(float* c, const uint32_t* a, const uint32_t* b) {
    asm volatile(
        "mma.sync.aligned.m16n8k8.row.col.f32.tf32.tf32.f32 "
        "{%0,%1,%2,%3}, {%4,%5,%6,%7}, {%8,%9}, {%0,%1,%2,%3};"
        : "+f"(c[0]), "+f"(c[1]), "+f"(c[2]), "+f"(c[3])
        : "r"(a[0]), "r"(a[1]), "r"(a[2]), "r"(a[3]), "r"(b[0]), "r"(b[1]));
}

// one K-chunk into stage: A[128][32] swizzled + B[256][32] swizzled
__device__ __forceinline__ void load_stage(uint32_t sb, uint32_t s_bytes, int c,
        const float* __restrict__ Ab, const float* __restrict__ We, int tid)
{
    const uint32_t st = sb + SM_STAGE_F * 4u + s_bytes;
    {   // A: 2 threads per row, 16 floats each
        const int row = tid >> 1, half = tid & 1;
        const float* g = Ab + (size_t)row * H_DIM + c * KC + half * 16;
        #pragma unroll
        for (int seg = 0; seg < 4; seg++) {
            const int col = half * 16 + seg * 4;
            const uint32_t sc = (uint32_t)((col + 4 * row) & 31);
            cp16(st + ((uint32_t)row * 32u + sc) * 4u, g + seg * 4);
        }
    }
    {   // B(=We): 1 thread per row, 32 floats
        const float* g = We + (size_t)tid * H_DIM + c * KC;
        #pragma unroll
        for (int seg = 0; seg < 8; seg++) {
            const int col = seg * 4;
            const uint32_t sc = (uint32_t)((col + 4 * tid) & 31);
            cp16(st + 128u * 32u * 4u + ((uint32_t)tid * 32u + sc) * 4u, g + seg * 4);
        }
    }
}

// ---------------- kernel 1: q-projection + bias fold ----------------
__global__ void __launch_bounds__(256) pa2_qc(
    const float* __restrict__ query, const float* __restrict__ Wq,
    const float* __restrict__ bq, const float* __restrict__ be)
{
    __shared__ float4 q4[128];
    const int bb = blockIdx.x, o = threadIdx.x;
    if (o < 128) q4[o] = ((const float4*)(query + (size_t)bb * 512))[o];
    __syncthreads();
    const float4* w = (const float4*)(Wq + (size_t)o * 512);
    float acc = 0.f;
    #pragma unroll 4
    for (int i = 0; i < 128; i++) {
        float4 a = w[i], q = q4[i];
        acc += a.x * q.x + a.y * q.y + a.z * q.z + a.w * q.w;
    }
    g_qc[bb * 256 + o] = acc + bq[o] + be[o];
}

// ---------------- kernel 2: GEMM + tanh-scorer epilogue ----------------
__global__ void __launch_bounds__(256, 1) pa2_main(
    const float* __restrict__ ref, const float* __restrict__ We,
    const float* __restrict__ Wv, const float* __restrict__ bv,
    float* __restrict__ out)
{
    extern __shared__ float smf[];
    const uint32_t sb = smem_u32(smf);
    const int tid  = threadIdx.x;
    const int lane = tid & 31;
    const int wid  = tid >> 5;
    const int q    = lane >> 2;       // groupID
    const int clo  = lane & 3;        // threadID_in_group
    const int wm   = wid >> 2;        // 0..1  (M)
    const int wn   = wid & 3;         // 0..3  (N)
    const long long rowbase = (long long)blockIdx.x * TM;
    const int b = blockIdx.x >> 3;    // 8 CTAs of 128 rows per batch (G=1024)

    float* cv   = smf;           // [256]
    float* wv   = smf + 256;     // [32]
    float* srow = smf + 288;     // [128]

    cv[tid] = g_qc[b * 256 + tid];
    if (tid < 32)  wv[tid]   = Wv[tid];
    if (tid < 128) srow[tid] = 0.f;

    const float* Ab = ref + rowbase * H_DIM;

    // prologue: chunks 0..2 -> stages 0..2
    #pragma unroll
    for (int c = 0; c < STAGES; c++) {
        load_stage(sb, (uint32_t)c * STAGE_FLOATS * 4u, c, Ab, We, tid);
        asm volatile("cp.async.commit_group;" ::: "memory");
    }

    float acc[128];
    #pragma unroll
    for (int t = 0; t < 128; t++) acc[t] = 0.f;

    int s_f = 0;   // stage offset in floats
    for (int c = 0; c < NCH; c++) {
        asm volatile("cp.async.wait_group 2;" ::: "memory");
        __syncthreads();

        const float* As = smf + SM_STAGE_F + s_f;   // [128][32] swizzled
        const float* Bs = As + 128 * 32;            // [256][32] swizzled

        #pragma unroll
        for (int ks = 0; ks < 4; ks++) {
            const int k0 = ks * 8 + clo;
            uint32_t af[4][4], bf[8][2];
            #pragma unroll
            for (int i = 0; i < 4; i++) {
                const int r0 = wm * 64 + i * 16 + q;
                const int r1 = r0 + 8;
                af[i][0] = f2tf(As[r0 * 32 + ((k0     + 4 * r0) & 31)]);
                af[i][1] = f2tf(As[r1 * 32 + ((k0     + 4 * r1) & 31)]);
                af[i][2] = f2tf(As[r0 * 32 + ((k0 + 4 + 4 * r0) & 31)]);
                af[i][3] = f2tf(As[r1 * 32 + ((k0 + 4 + 4 * r1) & 31)]);
            }
            #pragma unroll
            for (int j = 0; j < 8; j++) {
                const int n0 = wn * 64 + j * 8 + q;
                bf[j][0] = f2tf(Bs[n0 * 32 + ((k0     + 4 * n0) & 31)]);
                bf[j][1] = f2tf(Bs[n0 * 32 + ((k0 + 4 + 4 * n0) & 31)]);
            }
            #pragma unroll
            for (int i = 0; i < 4; i++)
                #pragma unroll
                for (int j = 0; j < 8; j++)
                    mma8(&acc[(i * 8 + j) * 4], af[i], bf[j]);
        }

        if (c + STAGES < NCH) {
            __syncthreads();   // everyone done reading this stage
            load_stage(sb, (uint32_t)s_f * 4u, c + STAGES, Ab, We, tid);
        }
        asm volatile("cp.async.commit_group;" ::: "memory");  // uniform accounting

        s_f += STAGE_FLOATS;
        if (s_f == STAGES * STAGE_FLOATS) s_f = 0;
    }

    // ---- epilogue: tanh + Wv dot, reduce over all 256 cols per row ----
    float ps[8];
    #pragma unroll
    for (int t = 0; t < 8; t++) ps[t] = 0.f;

    #pragma unroll
    for (int i = 0; i < 4; i++) {
        #pragma unroll
        for (int j = 0; j < 8; j++) {
            const int cb = wn * 64 + j * 8 + clo * 2;
            #pragma unroll
            for (int d = 0; d < 2; d++) {
                const int   col = cb + d;
                const float cvv = cv[col];
                const float wvv = wv[col & 31];
                // row r = wm*64 + i*16 + q  (c0/c1), row r+8 (c2/c3)
                float x0 = acc[(i * 8 + j) * 4 + d]     + cvv;
                float x1 = acc[(i * 8 + j) * 4 + 2 + d] + cvv;
                float t0 = __expf(x0 + x0);
                float t1 = __expf(x1 + x1);
                float th0 = 1.f - __fdividef(2.f, t0 + 1.f);   // tanh(x0)
                float th1 = 1.f - __fdividef(2.f, t1 + 1.f);   // tanh(x1)
                ps[i * 2]     = fmaf(th0, wvv, ps[i * 2]);
                ps[i * 2 + 1] = fmaf(th1, wvv, ps[i * 2 + 1]);
            }
        }
    }
    // reduce across the 4 lanes sharing each row
    #pragma unroll
    for (int t = 0; t < 8; t++) {
        ps[t] += __shfl_xor_sync(0xffffffffu, ps[t], 1);
        ps[t] += __shfl_xor_sync(0xffffffffu, ps[t], 2);
    }
    // cross-warp (N-dim) reduction into smem rows
    if (clo == 0) {
        #pragma unroll
        for (int i = 0; i < 4; i++) {
            atomicAdd(&srow[wm * 64 + i * 16 + q],     ps[i * 2]);
            atomicAdd(&srow[wm * 64 + i * 16 + q + 8], ps[i * 2 + 1]);
        }
    }
    __syncthreads();
    if (tid < 128)
        out[rowbase + tid] = srow[tid] + 8.f * bv[0];
}

// ---------------- launch ----------------
extern "C" void kernel_launch(void* const* d_in, const int* in_sizes, int n_in,
                              void* d_out, int out_size)
{
    const float* query = (const float*)d_in[0];
    const float* ref   = (const float*)d_in[1];
    const float* Wq    = (const float*)d_in[2];
    const float* bq    = (const float*)d_in[3];
    const float* We    = (const float*)d_in[4];
    const float* be    = (const float*)d_in[5];
    const float* Wv    = (const float*)d_in[6];
    const float* bv    = (const float*)d_in[7];
    float* out = (float*)d_out;

    cudaFuncSetAttribute(pa2_main, cudaFuncAttributeMaxDynamicSharedMemorySize, SMEM_TOTAL);
    pa2_qc<<<B_DIM, 256>>>(query, Wq, bq, be);
    pa2_main<<<(B_DIM * G_DIM) / TM, 256, SMEM_TOTAL>>>(ref, We, Wv, bv, out);
}

// round 6
// speedup vs baseline: 1.0393x; 1.0393x over previous
#include <cuda_runtime.h>
#include <cstdint>

// ============================================================================
// PointAttention2: out[b,0,g] = sum_{o<256} Wv[o%32]*tanh(qc[b][o] + e[b,g,o]) + 8*bv
//   qc = query@Wq.T + bq + be (tiny),  e = ref@We.T  (34 GFLOP GEMM).
// Base-ISA tensor path (ptxas target sm_103, no 'a'): mma.sync m16n8k8 tf32.
// R4 -> R5 changes:
//   - We pre-rounded to tf32 in prologue (g_We); A fed as raw fp32 bits
//     (HW truncation) -> zero cvt in mainloop.
//   - k-slot remap (slot clo <-> global 2clo, slot clo+4 <-> 2clo+1):
//     fragment loads become LDS.64 from plain row-major smem.
//   - 16B-granular XOR swizzle (cp.async-compatible), conflict-free LDS.64.
// ============================================================================

#define B_DIM   256
#define G_DIM   1024
#define H_DIM   256
#define TM      128                 // rows per CTA
#define KC      32                  // K chunk (floats)
#define NCH     8                   // 256/32
#define STAGES  3
#define A_FLOATS (128*32)
#define STAGE_FLOATS (128*32 + 256*32)   // A(4096) + B(8192) = 48KB
#define SM_STAGE_F   512
#define SMEM_TOTAL   ((SM_STAGE_F + STAGES*STAGE_FLOATS) * 4)   // 149504 B

__device__ float g_qc[B_DIM * H_DIM];   // q[b][o] + bq[o] + be[o]
__device__ float g_We[H_DIM * H_DIM];   // We pre-rounded to tf32

// ---------------- helpers ----------------
__device__ __forceinline__ uint32_t smem_u32(const void* p) {
    uint32_t a;
    asm("{ .reg .u64 t; cvta.to.shared.u64 t, %1; cvt.u32.u64 %0, t; }" : "=r"(a) : "l"(p));
    return a;
}
__device__ __forceinline__ void cp16(uint32_t dst, const float* src) {
    asm volatile("cp.async.cg.shared.global [%0], [%1], 16;" :: "r"(dst), "l"(src) : "memory");
}
__device__ __forceinline__ void mma8(float* c, uint32_t a0, uint32_t a1, uint32_t a2,
                                     uint32_t a3, uint32_t b0, uint32_t b1) {
    asm volatile(
        "mma.sync.aligned.m16n8k8.row.col.f32.tf32.tf32.f32 "
        "{%0,%1,%2,%3}, {%4,%5,%6,%7}, {%8,%9}, {%0,%1,%2,%3};"
        : "+f"(c[0]), "+f"(c[1]), "+f"(c[2]), "+f"(c[3])
        : "r"(a0), "r"(a1), "r"(a2), "r"(a3), "r"(b0), "r"(b1));
}

// one K-chunk into stage (plain row-major [row][32] + 16B XOR swizzle)
__device__ __forceinline__ void load_stage(uint32_t sb, uint32_t s_bytes, int c,
        const float* __restrict__ Ab, const float* __restrict__ Wep, int tid)
{
    const uint32_t st = sb + SM_STAGE_F * 4u + s_bytes;
    {   // A: 2 threads per row, 16 floats each
        const int row = tid >> 1, half = tid & 1;
        const float* g = Ab + (size_t)row * H_DIM + c * KC + half * 16;
        const uint32_t sw = (uint32_t)((row & 3) << 1);
        #pragma unroll
        for (int seg = 0; seg < 4; seg++) {
            const uint32_t t = ((uint32_t)(half * 4 + seg)) ^ sw;   // 16B unit
            cp16(st + (uint32_t)row * 128u + t * 16u, g + seg * 4);
        }
    }
    {   // B(=g_We): 1 thread per row, 32 floats
        const float* g = Wep + (size_t)tid * H_DIM + c * KC;
        const uint32_t sw = (uint32_t)((tid & 3) << 1);
        const uint32_t base = st + A_FLOATS * 4u + (uint32_t)tid * 128u;
        #pragma unroll
        for (int seg = 0; seg < 8; seg++) {
            const uint32_t t = ((uint32_t)seg) ^ sw;
            cp16(base + t * 16u, g + seg * 4);
        }
    }
}

// ---------------- kernel 1: q-projection + bias fold + We tf32 pre-round ----
__global__ void __launch_bounds__(256) pa2_qc(
    const float* __restrict__ query, const float* __restrict__ Wq,
    const float* __restrict__ bq, const float* __restrict__ be,
    const float* __restrict__ We)
{
    __shared__ float4 q4[128];
    const int bb = blockIdx.x, o = threadIdx.x;
    if (o < 128) q4[o] = ((const float4*)(query + (size_t)bb * 512))[o];
    // pre-round one We element per thread (grid 256x256 == We size)
    {
        uint32_t r;
        asm("cvt.rna.tf32.f32 %0, %1;" : "=r"(r) : "f"(We[bb * 256 + o]));
        g_We[bb * 256 + o] = __uint_as_float(r);
    }
    __syncthreads();
    const float4* w = (const float4*)(Wq + (size_t)o * 512);
    float acc = 0.f;
    #pragma unroll 4
    for (int i = 0; i < 128; i++) {
        float4 a = w[i], q = q4[i];
        acc += a.x * q.x + a.y * q.y + a.z * q.z + a.w * q.w;
    }
    g_qc[bb * 256 + o] = acc + bq[o] + be[o];
}

// ---------------- kernel 2: GEMM + tanh-scorer epilogue ----------------
__global__ void __launch_bounds__(256, 1) pa2_main(
    const float* __restrict__ ref,
    const float* __restrict__ Wv, const float* __restrict__ bv,
    float* __restrict__ out)
{
    extern __shared__ float smf[];
    const uint32_t sb = smem_u32(smf);
    const int tid  = threadIdx.x;
    const int lane = tid & 31;
    const int wid  = tid >> 5;
    const int q    = lane >> 2;       // groupID
    const int clo  = lane & 3;        // threadID_in_group
    const int wm   = wid >> 2;        // 0..1  (M)
    const int wn   = wid & 3;         // 0..3  (N)
    const long long rowbase = (long long)blockIdx.x * TM;
    const int b = blockIdx.x >> 3;    // 8 CTAs of 128 rows per batch

    float* cv   = smf;           // [256]
    float* wv   = smf + 256;     // [32]
    float* srow = smf + 288;     // [128]

    cv[tid] = g_qc[b * 256 + tid];
    if (tid < 32)  wv[tid]   = Wv[tid];
    if (tid < 128) srow[tid] = 0.f;

    const float* Ab = ref + rowbase * H_DIM;

    #pragma unroll
    for (int c = 0; c < STAGES; c++) {
        load_stage(sb, (uint32_t)c * STAGE_FLOATS * 4u, c, Ab, g_We, tid);
        asm volatile("cp.async.commit_group;" ::: "memory");
    }

    float acc[128];
    #pragma unroll
    for (int t = 0; t < 128; t++) acc[t] = 0.f;

    // fragment swizzle mask: 8B unit u' = (ks*4+clo) ^ ((row&3)<<2); row&3 == q&3
    const int kx = (q & 3) << 2;

    int s_f = 0;
    for (int c = 0; c < NCH; c++) {
        asm volatile("cp.async.wait_group 2;" ::: "memory");
        __syncthreads();

        const uint2* As2 = (const uint2*)(smf + SM_STAGE_F + s_f);          // [128][16]
        const uint2* Bs2 = As2 + 128 * 16;                                   // [256][16]

        #pragma unroll
        for (int ks = 0; ks < 4; ks++) {
            const int u = (ks * 4 + clo) ^ kx;      // swizzled 8B unit in row
            uint2 af[8];                            // i -> (r0, r1)
            uint2 bf[8];                            // j
            #pragma unroll
            for (int i = 0; i < 4; i++) {
                const int r0 = wm * 64 + i * 16 + q;
                af[i * 2]     = As2[r0 * 16 + u];
                af[i * 2 + 1] = As2[(r0 + 8) * 16 + u];
            }
            #pragma unroll
            for (int j = 0; j < 8; j++) {
                const int n0 = wn * 64 + j * 8 + q;
                bf[j] = Bs2[n0 * 16 + u];
            }
            #pragma unroll
            for (int i = 0; i < 4; i++)
                #pragma unroll
                for (int j = 0; j < 8; j++)
                    mma8(&acc[(i * 8 + j) * 4],
                         af[i * 2].x, af[i * 2 + 1].x, af[i * 2].y, af[i * 2 + 1].y,
                         bf[j].x, bf[j].y);
        }

        if (c + STAGES < NCH) {
            __syncthreads();
            load_stage(sb, (uint32_t)s_f * 4u, c + STAGES, Ab, g_We, tid);
        }
        asm volatile("cp.async.commit_group;" ::: "memory");  // uniform accounting

        s_f += STAGE_FLOATS;
        if (s_f == STAGES * STAGE_FLOATS) s_f = 0;
    }

    // ---- epilogue: tanh + Wv dot, reduce over 256 cols per row ----
    float ps[8];
    #pragma unroll
    for (int t = 0; t < 8; t++) ps[t] = 0.f;

    #pragma unroll
    for (int i = 0; i < 4; i++) {
        #pragma unroll
        for (int j = 0; j < 8; j++) {
            const int cb = wn * 64 + j * 8 + clo * 2;
            #pragma unroll
            for (int d = 0; d < 2; d++) {
                const int   col = cb + d;
                const float cvv = cv[col];
                const float wvv = wv[col & 31];
                float x0 = acc[(i * 8 + j) * 4 + d]     + cvv;
                float x1 = acc[(i * 8 + j) * 4 + 2 + d] + cvv;
                float t0 = __expf(x0 + x0);
                float t1 = __expf(x1 + x1);
                float th0 = 1.f - __fdividef(2.f, t0 + 1.f);
                float th1 = 1.f - __fdividef(2.f, t1 + 1.f);
                ps[i * 2]     = fmaf(th0, wvv, ps[i * 2]);
                ps[i * 2 + 1] = fmaf(th1, wvv, ps[i * 2 + 1]);
            }
        }
    }
    #pragma unroll
    for (int t = 0; t < 8; t++) {
        ps[t] += __shfl_xor_sync(0xffffffffu, ps[t], 1);
        ps[t] += __shfl_xor_sync(0xffffffffu, ps[t], 2);
    }
    if (clo == 0) {
        #pragma unroll
        for (int i = 0; i < 4; i++) {
            atomicAdd(&srow[wm * 64 + i * 16 + q],     ps[i * 2]);
            atomicAdd(&srow[wm * 64 + i * 16 + q + 8], ps[i * 2 + 1]);
        }
    }
    __syncthreads();
    if (tid < 128)
        out[rowbase + tid] = srow[tid] + 8.f * bv[0];
}

// ---------------- launch ----------------
extern "C" void kernel_launch(void* const* d_in, const int* in_sizes, int n_in,
                              void* d_out, int out_size)
{
    const float* query = (const float*)d_in[0];
    const float* ref   = (const float*)d_in[1];
    const float* Wq    = (const float*)d_in[2];
    const float* bq    = (const float*)d_in[3];
    const float* We    = (const float*)d_in[4];
    const float* be    = (const float*)d_in[5];
    const float* Wv    = (const float*)d_in[6];
    const float* bv    = (const float*)d_in[7];
    float* out = (float*)d_out;

    cudaFuncSetAttribute(pa2_main, cudaFuncAttributeMaxDynamicSharedMemorySize, SMEM_TOTAL);
    pa2_qc<<<B_DIM, 256>>>(query, Wq, bq, be, We);
    pa2_main<<<(B_DIM * G_DIM) / TM, 256, SMEM_TOTAL>>>(ref, Wv, bv, out);
}

// round 7
// speedup vs baseline: 1.2362x; 1.1894x over previous
#include <cuda_runtime.h>
#include <cstdint>

// ============================================================================
// PointAttention2: out[b,0,g] = sum_{o<256} Wv[o%32]*tanh(qc[b][o] + e[b,g,o]) + 8*bv
//   qc = query@Wq.T + bq + be (tiny),  e = ref@We.T  (34 GFLOP GEMM).
// Base-ISA tensor path (ptxas target sm_103, no 'a'): mma.sync m16n8k8 tf32.
// R5 -> R6: occupancy fix. 512 threads (16 warps, 4/SMSP), warp grid 4x4,
// warp tile 32x64 (64 acc regs), 4-stage cp.async pipeline. Same CTA tile
// 128x256, same 16B XOR swizzle + LDS.64 fragments, We pre-rounded to tf32.
// ============================================================================

#define B_DIM   256
#define G_DIM   1024
#define H_DIM   256
#define TM      128                 // rows per CTA
#define KC      32                  // K chunk (floats)
#define NCH     8                   // 256/32
#define STAGES  4
#define THREADS 512
#define A_FLOATS (128*32)
#define STAGE_FLOATS (128*32 + 256*32)   // A(4096) + B(8192) floats = 48KB
#define SM_STAGE_F   512
#define SMEM_TOTAL   ((SM_STAGE_F + STAGES*STAGE_FLOATS) * 4)   // 198656 B

__device__ float g_qc[B_DIM * H_DIM];   // q[b][o] + bq[o] + be[o]
__device__ float g_We[H_DIM * H_DIM];   // We pre-rounded to tf32

// ---------------- helpers ----------------
__device__ __forceinline__ uint32_t smem_u32(const void* p) {
    uint32_t a;
    asm("{ .reg .u64 t; cvta.to.shared.u64 t, %1; cvt.u32.u64 %0, t; }" : "=r"(a) : "l"(p));
    return a;
}
__device__ __forceinline__ void cp16(uint32_t dst, const float* src) {
    asm volatile("cp.async.cg.shared.global [%0], [%1], 16;" :: "r"(dst), "l"(src) : "memory");
}
__device__ __forceinline__ void mma8(float* c, uint32_t a0, uint32_t a1, uint32_t a2,
                                     uint32_t a3, uint32_t b0, uint32_t b1) {
    asm volatile(
        "mma.sync.aligned.m16n8k8.row.col.f32.tf32.tf32.f32 "
        "{%0,%1,%2,%3}, {%4,%5,%6,%7}, {%8,%9}, {%0,%1,%2,%3};"
        : "+f"(c[0]), "+f"(c[1]), "+f"(c[2]), "+f"(c[3])
        : "r"(a0), "r"(a1), "r"(a2), "r"(a3), "r"(b0), "r"(b1));
}

// one K-chunk into stage (row-major [row][32 floats], 16B XOR swizzle)
// 512 threads: A = 2 cp16/thread (4 threads/row), B = 4 cp16/thread (2 threads/row)
__device__ __forceinline__ void load_stage(uint32_t sb, uint32_t s_bytes, int c,
        const float* __restrict__ Ab, const float* __restrict__ Wep, int tid)
{
    const uint32_t st = sb + SM_STAGE_F * 4u + s_bytes;
    {   // A: 128 rows, 4 threads per row, 8 floats (2 x 16B) each
        const int row = tid >> 2, quar = tid & 3;
        const float* g = Ab + (size_t)row * H_DIM + c * KC + quar * 8;
        const uint32_t sw = (uint32_t)((row & 3) << 1);
        #pragma unroll
        for (int seg = 0; seg < 2; seg++) {
            const uint32_t t = ((uint32_t)(quar * 2 + seg)) ^ sw;   // 16B unit
            cp16(st + (uint32_t)row * 128u + t * 16u, g + seg * 4);
        }
    }
    {   // B(=g_We): 256 rows, 2 threads per row, 16 floats (4 x 16B) each
        const int row = tid >> 1, half = tid & 1;
        const float* g = Wep + (size_t)row * H_DIM + c * KC + half * 16;
        const uint32_t sw = (uint32_t)((row & 3) << 1);
        const uint32_t base = st + A_FLOATS * 4u + (uint32_t)row * 128u;
        #pragma unroll
        for (int seg = 0; seg < 4; seg++) {
            const uint32_t t = ((uint32_t)(half * 4 + seg)) ^ sw;
            cp16(base + t * 16u, g + seg * 4);
        }
    }
}

// ---------------- kernel 1: q-projection + bias fold + We tf32 pre-round ----
__global__ void __launch_bounds__(256) pa2_qc(
    const float* __restrict__ query, const float* __restrict__ Wq,
    const float* __restrict__ bq, const float* __restrict__ be,
    const float* __restrict__ We)
{
    __shared__ float4 q4[128];
    const int bb = blockIdx.x, o = threadIdx.x;
    if (o < 128) q4[o] = ((const float4*)(query + (size_t)bb * 512))[o];
    {
        uint32_t r;
        asm("cvt.rna.tf32.f32 %0, %1;" : "=r"(r) : "f"(We[bb * 256 + o]));
        g_We[bb * 256 + o] = __uint_as_float(r);
    }
    __syncthreads();
    const float4* w = (const float4*)(Wq + (size_t)o * 512);
    float acc = 0.f;
    #pragma unroll 4
    for (int i = 0; i < 128; i++) {
        float4 a = w[i], q = q4[i];
        acc += a.x * q.x + a.y * q.y + a.z * q.z + a.w * q.w;
    }
    g_qc[bb * 256 + o] = acc + bq[o] + be[o];
}

// ---------------- kernel 2: GEMM + tanh-scorer epilogue ----------------
__global__ void __launch_bounds__(THREADS, 1) pa2_main(
    const float* __restrict__ ref,
    const float* __restrict__ Wv, const float* __restrict__ bv,
    float* __restrict__ out)
{
    extern __shared__ float smf[];
    const uint32_t sb = smem_u32(smf);
    const int tid  = threadIdx.x;
    const int lane = tid & 31;
    const int wid  = tid >> 5;        // 0..15
    const int q    = lane >> 2;       // groupID 0..7
    const int clo  = lane & 3;        // threadID_in_group
    const int wm   = wid >> 2;        // 0..3  (M): rows wm*32..+31
    const int wn   = wid & 3;         // 0..3  (N): cols wn*64..+63
    const long long rowbase = (long long)blockIdx.x * TM;
    const int b = blockIdx.x >> 3;    // 8 CTAs of 128 rows per batch

    float* cv   = smf;           // [256]
    float* wv   = smf + 256;     // [32]
    float* srow = smf + 288;     // [128]

    if (tid < 256) cv[tid] = g_qc[b * 256 + tid];
    if (tid < 32)  wv[tid]   = Wv[tid];
    if (tid < 128) srow[tid] = 0.f;

    const float* Ab = ref + rowbase * H_DIM;

    #pragma unroll
    for (int c = 0; c < STAGES; c++) {
        load_stage(sb, (uint32_t)c * STAGE_FLOATS * 4u, c, Ab, g_We, tid);
        asm volatile("cp.async.commit_group;" ::: "memory");
    }

    float acc[64];
    #pragma unroll
    for (int t = 0; t < 64; t++) acc[t] = 0.f;

    // fragment swizzle: 8B unit u' = (ks*4+clo) ^ ((q&3)<<2)
    const int kx = (q & 3) << 2;

    int s_f = 0;
    for (int c = 0; c < NCH; c++) {
        asm volatile("cp.async.wait_group 3;" ::: "memory");
        __syncthreads();

        const uint2* As2 = (const uint2*)(smf + SM_STAGE_F + s_f);   // [128][16]
        const uint2* Bs2 = As2 + 128 * 16;                            // [256][16]

        #pragma unroll
        for (int ks = 0; ks < 4; ks++) {
            const int u = (ks * 4 + clo) ^ kx;
            uint2 af[4];     // i in {0,1} -> (r0, r0+8)
            uint2 bf[8];
            #pragma unroll
            for (int i = 0; i < 2; i++) {
                const int r0 = wm * 32 + i * 16 + q;
                af[i * 2]     = As2[r0 * 16 + u];
                af[i * 2 + 1] = As2[(r0 + 8) * 16 + u];
            }
            #pragma unroll
            for (int j = 0; j < 8; j++) {
                const int n0 = wn * 64 + j * 8 + q;
                bf[j] = Bs2[n0 * 16 + u];
            }
            #pragma unroll
            for (int i = 0; i < 2; i++)
                #pragma unroll
                for (int j = 0; j < 8; j++)
                    mma8(&acc[(i * 8 + j) * 4],
                         af[i * 2].x, af[i * 2 + 1].x, af[i * 2].y, af[i * 2 + 1].y,
                         bf[j].x, bf[j].y);
        }

        if (c + STAGES < NCH) {
            __syncthreads();   // everyone done reading stage s before overwrite
            load_stage(sb, (uint32_t)s_f * 4u, c + STAGES, Ab, g_We, tid);
        }
        asm volatile("cp.async.commit_group;" ::: "memory");  // uniform accounting

        s_f += STAGE_FLOATS;
        if (s_f == STAGES * STAGE_FLOATS) s_f = 0;
    }

    // ---- epilogue: tanh + Wv dot over this warp's 64 cols, 32 rows ----
    float ps[4];
    #pragma unroll
    for (int t = 0; t < 4; t++) ps[t] = 0.f;

    #pragma unroll
    for (int i = 0; i < 2; i++) {
        #pragma unroll
        for (int j = 0; j < 8; j++) {
            const int cb = wn * 64 + j * 8 + clo * 2;
            #pragma unroll
            for (int d = 0; d < 2; d++) {
                const int   col = cb + d;
                const float cvv = cv[col];
                const float wvv = wv[col & 31];
                float x0 = acc[(i * 8 + j) * 4 + d]     + cvv;   // row wm*32+i*16+q
                float x1 = acc[(i * 8 + j) * 4 + 2 + d] + cvv;   // row +8
                float t0 = __expf(x0 + x0);
                float t1 = __expf(x1 + x1);
                float th0 = 1.f - __fdividef(2.f, t0 + 1.f);
                float th1 = 1.f - __fdividef(2.f, t1 + 1.f);
                ps[i * 2]     = fmaf(th0, wvv, ps[i * 2]);
                ps[i * 2 + 1] = fmaf(th1, wvv, ps[i * 2 + 1]);
            }
        }
    }
    #pragma unroll
    for (int t = 0; t < 4; t++) {
        ps[t] += __shfl_xor_sync(0xffffffffu, ps[t], 1);
        ps[t] += __shfl_xor_sync(0xffffffffu, ps[t], 2);
    }
    if (clo == 0) {
        #pragma unroll
        for (int i = 0; i < 2; i++) {
            atomicAdd(&srow[wm * 32 + i * 16 + q],     ps[i * 2]);
            atomicAdd(&srow[wm * 32 + i * 16 + q + 8], ps[i * 2 + 1]);
        }
    }
    __syncthreads();
    if (tid < 128)
        out[rowbase + tid] = srow[tid] + 8.f * bv[0];
}

// ---------------- launch ----------------
extern "C" void kernel_launch(void* const* d_in, const int* in_sizes, int n_in,
                              void* d_out, int out_size)
{
    const float* query = (const float*)d_in[0];
    const float* ref   = (const float*)d_in[1];
    const float* Wq    = (const float*)d_in[2];
    const float* bq    = (const float*)d_in[3];
    const float* We    = (const float*)d_in[4];
    const float* be    = (const float*)d_in[5];
    const float* Wv    = (const float*)d_in[6];
    const float* bv    = (const float*)d_in[7];
    float* out = (float*)d_out;

    cudaFuncSetAttribute(pa2_main, cudaFuncAttributeMaxDynamicSharedMemorySize, SMEM_TOTAL);
    pa2_qc<<<B_DIM, 256>>>(query, Wq, bq, be, We);
    pa2_main<<<(B_DIM * G_DIM) / TM, THREADS, SMEM_TOTAL>>>(ref, Wv, bv, out);
}

// round 9
// speedup vs baseline: 1.2627x; 1.0214x over previous
#include <cuda_runtime.h>
#include <cstdint>

// ============================================================================
// PointAttention2: out[b,0,g] = sum_{o<256} Wv[o%32]*tanh(qc[b][o] + e[b,g,o]) + 8*bv
//   qc = query@Wq.T + bq + be (tiny),  e = ref@We.T  (34 GFLOP GEMM).
// Base-ISA tensor path (ptxas target sm_103, no 'a'): mma.sync m16n8k8 tf32.
// R6 -> R7 (scheduling round, numerics identical):
//   - LDS.128 fragments via k-slot remap (24 LDS.128/warp/chunk vs 48 LDS.64)
//   - swizzle s(row) = ((row&1)<<2)^(row&3) on 16B units: conflict-free for
//     cp.async stores AND LDS.128 fragment loads
//   - ONE __syncthreads per chunk (wait -> sync -> load c+3 -> mma c)
//   - per-warp P-phase rotation to decorrelate pipe bursts within an SMSP
//   - pa2_qc: 4 batch rows per block (4x Wq reuse)
// ============================================================================

#define B_DIM   256
#define G_DIM   1024
#define H_DIM   256
#define TM      128
#define NCH     8
#define STAGES  4
#define THREADS 512
#define A_BYTES (128*128)                 // 16 KB A per stage
#define STAGE_BYTES ((128+256)*128)       // 48 KB per stage
#define SM_RES_BYTES 2048                 // cv/wv/srow region
#define SMEM_TOTAL (SM_RES_BYTES + STAGES*STAGE_BYTES)   // 198656 B

__device__ float g_qc[B_DIM * H_DIM];   // q[b][o] + bq[o] + be[o]
__device__ float g_We[H_DIM * H_DIM];   // We pre-rounded to tf32

// ---------------- helpers ----------------
__device__ __forceinline__ uint32_t smem_u32(const void* p) {
    uint32_t a;
    asm("{ .reg .u64 t; cvta.to.shared.u64 t, %1; cvt.u32.u64 %0, t; }" : "=r"(a) : "l"(p));
    return a;
}
__device__ __forceinline__ void cp16(uint32_t dst, const float* src) {
    asm volatile("cp.async.cg.shared.global [%0], [%1], 16;" :: "r"(dst), "l"(src) : "memory");
}
__device__ __forceinline__ uint4 lds128(uint32_t a) {
    uint4 v;
    asm("ld.shared.v4.b32 {%0,%1,%2,%3}, [%4];"
        : "=r"(v.x), "=r"(v.y), "=r"(v.z), "=r"(v.w) : "r"(a));
    return v;
}
__device__ __forceinline__ void mma8(float* c, uint32_t a0, uint32_t a1, uint32_t a2,
                                     uint32_t a3, uint32_t b0, uint32_t b1) {
    asm volatile(
        "mma.sync.aligned.m16n8k8.row.col.f32.tf32.tf32.f32 "
        "{%0,%1,%2,%3}, {%4,%5,%6,%7}, {%8,%9}, {%0,%1,%2,%3};"
        : "+f"(c[0]), "+f"(c[1]), "+f"(c[2]), "+f"(c[3])
        : "r"(a0), "r"(a1), "r"(a2), "r"(a3), "r"(b0), "r"(b1));
}

// one K-chunk (32 floats) into the stage at wb. 16B-unit swizzle s(row).
__device__ __forceinline__ void load_stage(uint32_t wb, int c,
        const float* __restrict__ Ab, int tid)
{
    {   // A: 128 rows, 4 threads/row, 2 x cp16 each
        const int row = tid >> 2, quar = tid & 3;
        const uint32_t s = (uint32_t)(((row & 1) << 2) ^ (row & 3));
        const float* g = Ab + (size_t)row * H_DIM + c * 32 + quar * 8;
        #pragma unroll
        for (int seg = 0; seg < 2; seg++) {
            const uint32_t u = ((uint32_t)(quar * 2 + seg)) ^ s;
            cp16(wb + (uint32_t)row * 128u + u * 16u, g + seg * 4);
        }
    }
    {   // B(=g_We): 256 rows, 2 threads/row, 4 x cp16 each
        const int row = tid >> 1, half = tid & 1;
        const uint32_t s = (uint32_t)(((row & 1) << 2) ^ (row & 3));
        const float* g = g_We + (size_t)row * H_DIM + c * 32 + half * 16;
        const uint32_t base = wb + A_BYTES + (uint32_t)row * 128u;
        #pragma unroll
        for (int seg = 0; seg < 4; seg++) {
            const uint32_t u = ((uint32_t)(half * 4 + seg)) ^ s;
            cp16(base + u * 16u, g + seg * 4);
        }
    }
}

// ---------------- kernel 1: q-projection (4 b-rows/block) + We pre-round ----
__global__ void __launch_bounds__(256) pa2_qc(
    const float* __restrict__ query, const float* __restrict__ Wq,
    const float* __restrict__ bq, const float* __restrict__ be,
    const float* __restrict__ We)
{
    __shared__ float4 q4[4][128];
    const int o = threadIdx.x;
    const int b0 = blockIdx.x * 4;
    // load 4 query rows (4*128 float4)
    #pragma unroll
    for (int t = o; t < 512; t += 256)
        q4[t >> 7][t & 127] = ((const float4*)query)[(size_t)b0 * 128 + t];
    // pre-round 4 We elements per thread (grid 64 * 256 * 4 == 65536)
    #pragma unroll
    for (int t = o; t < 1024; t += 256) {
        const int idx = blockIdx.x * 1024 + t;
        uint32_t r;
        asm("cvt.rna.tf32.f32 %0, %1;" : "=r"(r) : "f"(We[idx]));
        g_We[idx] = __uint_as_float(r);
    }
    __syncthreads();
    const float4* w = (const float4*)(Wq + (size_t)o * 512);
    float a0 = 0.f, a1 = 0.f, a2 = 0.f, a3 = 0.f;
    #pragma unroll 4
    for (int i = 0; i < 128; i++) {
        const float4 wv = w[i];
        float4 v;
        v = q4[0][i]; a0 += wv.x * v.x + wv.y * v.y + wv.z * v.z + wv.w * v.w;
        v = q4[1][i]; a1 += wv.x * v.x + wv.y * v.y + wv.z * v.z + wv.w * v.w;
        v = q4[2][i]; a2 += wv.x * v.x + wv.y * v.y + wv.z * v.z + wv.w * v.w;
        v = q4[3][i]; a3 += wv.x * v.x + wv.y * v.y + wv.z * v.z + wv.w * v.w;
    }
    const float bias = bq[o] + be[o];
    g_qc[(b0 + 0) * 256 + o] = a0 + bias;
    g_qc[(b0 + 1) * 256 + o] = a1 + bias;
    g_qc[(b0 + 2) * 256 + o] = a2 + bias;
    g_qc[(b0 + 3) * 256 + o] = a3 + bias;
}

// ---------------- kernel 2: GEMM + tanh-scorer epilogue ----------------
__global__ void __launch_bounds__(THREADS, 1) pa2_main(
    const float* __restrict__ ref,
    const float* __restrict__ Wv, const float* __restrict__ bv,
    float* __restrict__ out)
{
    extern __shared__ float smf[];
    const uint32_t sb = smem_u32(smf);
    const int tid  = threadIdx.x;
    const int lane = tid & 31;
    const int wid  = tid >> 5;        // 0..15
    const int q    = lane >> 2;       // groupID 0..7
    const int clo  = lane & 3;
    const int wm   = wid >> 2;        // M: rows wm*32..+31
    const int wn   = wid & 3;         // N: cols wn*64..+63
    const int ph   = (wid >> 2) & 1;  // P-phase rotation (varies within SMSP)
    const long long rowbase = (long long)blockIdx.x * TM;
    const int b = blockIdx.x >> 3;

    float* cv   = smf;           // [256]
    float* wv   = smf + 256;     // [32]
    float* srow = smf + 288;     // [128]

    if (tid < 256) cv[tid] = g_qc[b * 256 + tid];
    if (tid < 32)  wv[tid]   = Wv[tid];
    if (tid < 128) srow[tid] = 0.f;

    const float* Ab = ref + rowbase * H_DIM;

    // fragment addressing constants
    const int s_q = ((q & 1) << 2) ^ (q & 3);
    const uint32_t u0   = (uint32_t)((clo ^ s_q) << 4);
    const uint32_t aoff = (uint32_t)((wm * 32 + q) * 128);
    const uint32_t boff = (uint32_t)(A_BYTES + (wn * 64 + q) * 128);

    // prologue: chunks 0..2 -> stages 0..2
    #pragma unroll
    for (int c = 0; c < 3; c++) {
        load_stage(sb + SM_RES_BYTES + (uint32_t)c * STAGE_BYTES, c, Ab, tid);
        asm volatile("cp.async.commit_group;" ::: "memory");
    }

    float acc[64];
    #pragma unroll
    for (int t = 0; t < 64; t++) acc[t] = 0.f;

    uint32_t stg = sb + SM_RES_BYTES;                       // read stage (c&3)
    uint32_t wst = sb + SM_RES_BYTES + 3u * STAGE_BYTES;    // write stage ((c+3)&3)
    const uint32_t stg_hi = sb + SM_RES_BYTES + 4u * STAGE_BYTES;

    for (int c = 0; c < NCH; c++) {
        asm volatile("cp.async.wait_group 2;" ::: "memory");
        __syncthreads();

        if (c + 3 < NCH) load_stage(wst, c + 3, Ab, tid);
        asm volatile("cp.async.commit_group;" ::: "memory");  // real or empty

        const uint32_t stg_u = stg + u0;
        #pragma unroll
        for (int pp = 0; pp < 2; pp++) {
            const uint32_t stgP = stg_u ^ ((uint32_t)((pp ^ ph) << 6));
            uint4 aF[4], bF[4];
            #pragma unroll
            for (int i4 = 0; i4 < 4; i4++)
                aF[i4] = lds128(stgP + aoff + (uint32_t)i4 * 1024u);
            #pragma unroll
            for (int j = 0; j < 4; j++)
                bF[j] = lds128(stgP + boff + (uint32_t)j * 1024u);
            #pragma unroll
            for (int i = 0; i < 2; i++)
                #pragma unroll
                for (int j = 0; j < 4; j++) {
                    mma8(&acc[(i * 8 + j) * 4],
                         aF[2*i].x, aF[2*i+1].x, aF[2*i].y, aF[2*i+1].y,
                         bF[j].x, bF[j].y);
                    mma8(&acc[(i * 8 + j) * 4],
                         aF[2*i].z, aF[2*i+1].z, aF[2*i].w, aF[2*i+1].w,
                         bF[j].z, bF[j].w);
                }
            #pragma unroll
            for (int j = 0; j < 4; j++)
                bF[j] = lds128(stgP + boff + 4096u + (uint32_t)j * 1024u);
            #pragma unroll
            for (int i = 0; i < 2; i++)
                #pragma unroll
                for (int j = 0; j < 4; j++) {
                    mma8(&acc[(i * 8 + 4 + j) * 4],
                         aF[2*i].x, aF[2*i+1].x, aF[2*i].y, aF[2*i+1].y,
                         bF[j].x, bF[j].y);
                    mma8(&acc[(i * 8 + 4 + j) * 4],
                         aF[2*i].z, aF[2*i+1].z, aF[2*i].w, aF[2*i+1].w,
                         bF[j].z, bF[j].w);
                }
        }

        stg += STAGE_BYTES; if (stg == stg_hi) stg = sb + SM_RES_BYTES;
        wst += STAGE_BYTES; if (wst == stg_hi) wst = sb + SM_RES_BYTES;
    }

    // ---- epilogue: tanh + Wv dot over this warp's 64 cols, 32 rows ----
    float ps[4];
    #pragma unroll
    for (int t = 0; t < 4; t++) ps[t] = 0.f;

    #pragma unroll
    for (int i = 0; i < 2; i++) {
        #pragma unroll
        for (int j = 0; j < 8; j++) {
            const int cb = wn * 64 + j * 8 + clo * 2;
            #pragma unroll
            for (int d = 0; d < 2; d++) {
                const int   col = cb + d;
                const float cvv = cv[col];
                const float wvv = wv[col & 31];
                float x0 = acc[(i * 8 + j) * 4 + d]     + cvv;   // row wm*32+i*16+q
                float x1 = acc[(i * 8 + j) * 4 + 2 + d] + cvv;   // row +8
                float t0 = __expf(x0 + x0);
                float t1 = __expf(x1 + x1);
                float th0 = 1.f - __fdividef(2.f, t0 + 1.f);
                float th1 = 1.f - __fdividef(2.f, t1 + 1.f);
                ps[i * 2]     = fmaf(th0, wvv, ps[i * 2]);
                ps[i * 2 + 1] = fmaf(th1, wvv, ps[i * 2 + 1]);
            }
        }
    }
    #pragma unroll
    for (int t = 0; t < 4; t++) {
        ps[t] += __shfl_xor_sync(0xffffffffu, ps[t], 1);
        ps[t] += __shfl_xor_sync(0xffffffffu, ps[t], 2);
    }
    if (clo == 0) {
        #pragma unroll
        for (int i = 0; i < 2; i++) {
            atomicAdd(&srow[wm * 32 + i * 16 + q],     ps[i * 2]);
            atomicAdd(&srow[wm * 32 + i * 16 + q + 8], ps[i * 2 + 1]);
        }
    }
    __syncthreads();
    if (tid < 128)
        out[rowbase + tid] = srow[tid] + 8.f * bv[0];
}

// ---------------- launch ----------------
extern "C" void kernel_launch(void* const* d_in, const int* in_sizes, int n_in,
                              void* d_out, int out_size)
{
    const float* query = (const float*)d_in[0];
    const float* ref   = (const float*)d_in[1];
    const float* Wq    = (const float*)d_in[2];
    const float* bq    = (const float*)d_in[3];
    const float* We    = (const float*)d_in[4];
    const float* be    = (const float*)d_in[5];
    const float* Wv    = (const float*)d_in[6];
    const float* bv    = (const float*)d_in[7];
    float* out = (float*)d_out;

    cudaFuncSetAttribute(pa2_main, cudaFuncAttributeMaxDynamicSharedMemorySize, SMEM_TOTAL);
    pa2_qc<<<B_DIM / 4, 256>>>(query, Wq, bq, be, We);
    pa2_main<<<(B_DIM * G_DIM) / TM, THREADS, SMEM_TOTAL>>>(ref, Wv, bv, out);
}